// round 12
// baseline (speedup 1.0000x reference)
#include <cuda_runtime.h>
#include <cstdint>
#include <cstddef>

// ---------------- tile config ----------------
#define M_TILE 128
#define N_OUT  256
#define K_DIM  512
#define KC     16                  // K per pipeline stage
#define NCHUNK (K_DIM / KC)        // 32
#define STAGES 4
#define AST    20                  // padded fp32 stride -> conflict-free frags
#define NTHREADS 256
#define NT_H   9                   // n-tiles per HMMA warp (72 cols); HMMA covers cols [0,144)
#define CF0    144                 // FFMA col base; FFMA covers cols [144,256)

// smem float offsets
#define OFF_BIAS 0                 // 256
#define OFF_PT   256               // [3][128] partial t   (slot0/1: HMMA colgroups, slot2: FFMA)
#define OFF_PZZ  640               // [3][128] partial zz
#define OFF_AB   1024              // [2][128] alpha, beta
#define OFF_STG  2048
#define STG_FLTS (M_TILE * AST + N_OUT * AST)   // 7680
#define SMEM_FLTS (OFF_STG + STAGES * STG_FLTS) // 32768
#define SMEM_BYTES (SMEM_FLTS * 4)              // 131072

__device__ __forceinline__ uint32_t s2u(const void* p) {
    uint32_t a;
    asm("{ .reg .u64 t; cvta.to.shared.u64 t, %1; cvt.u32.u64 %0, t; }" : "=r"(a) : "l"(p));
    return a;
}
__device__ __forceinline__ void cp16(uint32_t dst, const float* src) {
    asm volatile("cp.async.cg.shared.global [%0], [%1], 16;" :: "r"(dst), "l"(src) : "memory");
}
__device__ __forceinline__ uint32_t f2tf32(float x) {
    uint32_t r;
    asm("cvt.rna.tf32.f32 %0, %1;" : "=r"(r) : "f"(x));
    return r;
}
__device__ __forceinline__ void mma_tf32(float* c, const uint32_t a[4], const uint32_t b[2]) {
    asm volatile(
        "mma.sync.aligned.m16n8k8.row.col.f32.tf32.tf32.f32 "
        "{%0,%1,%2,%3}, {%4,%5,%6,%7}, {%8,%9}, {%0,%1,%2,%3};"
        : "+f"(c[0]), "+f"(c[1]), "+f"(c[2]), "+f"(c[3])
        : "r"(a[0]), "r"(a[1]), "r"(a[2]), "r"(a[3]), "r"(b[0]), "r"(b[1]));
}
__device__ __forceinline__ unsigned long long fma2(unsigned long long a,
                                                   unsigned long long b,
                                                   unsigned long long c) {
    unsigned long long d;
    asm("fma.rn.f32x2 %0, %1, %2, %3;" : "=l"(d) : "l"(a), "l"(b), "l"(c));
    return d;
}
__device__ __forceinline__ unsigned long long pack2(float lo, float hi) {
    unsigned long long u;
    asm("mov.b64 %0, {%1, %2};" : "=l"(u) : "f"(lo), "f"(hi));
    return u;
}
__device__ __forceinline__ void unpack2(unsigned long long u, float& lo, float& hi) {
    asm("mov.b64 {%0, %1}, %2;" : "=f"(lo), "=f"(hi) : "l"(u));
}

__global__ void __launch_bounds__(NTHREADS, 1)
fused_gemm_proj_kernel(const float* __restrict__ x,
                       const float* __restrict__ Wm,
                       const float* __restrict__ bvec,
                       float* __restrict__ out) {
    extern __shared__ __align__(128) float sm[];
    const uint32_t sb = s2u(sm);
    const int tid  = threadIdx.x;
    const int wid  = tid >> 5;
    const int lane = tid & 31;
    const int m0   = blockIdx.x * M_TILE;

    sm[OFF_BIAS + tid] = bvec[tid];

    // ---- cp.async stage issue (all 256 threads) ----
    auto issue = [&](int k, int s) {
        const int k0 = k * KC;
        const uint32_t as = sb + (OFF_STG + s * STG_FLTS) * 4;
        const uint32_t bs = as + M_TILE * AST * 4;
        #pragma unroll
        for (int i = 0; i < 2; i++) {                  // A: 512 x 16B chunks
            const int ch = tid + NTHREADS * i;
            const int r = ch >> 2, c = (ch & 3) * 4;
            cp16(as + (r * AST + c) * 4, x + (size_t)(m0 + r) * K_DIM + k0 + c);
        }
        #pragma unroll
        for (int i = 0; i < 4; i++) {                  // W: 1024 x 16B chunks
            const int ch = tid + NTHREADS * i;
            const int n = ch >> 2, c = (ch & 3) * 4;
            cp16(bs + (n * AST + c) * 4, Wm + (size_t)n * K_DIM + k0 + c);
        }
    };

    // prologue
    #pragma unroll
    for (int s = 0; s < STAGES - 1; s++) {
        issue(s, s);
        asm volatile("cp.async.commit_group;" ::: "memory");
    }

    if (wid < 4) {
        // ================= HMMA warps: rows 128, cols [0,144) =================
        const int g   = lane >> 2;
        const int tg  = lane & 3;
        const int wrH = wid & 1;               // row group (64 rows)
        const int wcH = wid >> 1;              // col group (72 cols)
        const int rm  = wrH * 64;
        const int cn  = wcH * 72;

        float acc[4][NT_H][4];
        #pragma unroll
        for (int mt = 0; mt < 4; mt++)
            #pragma unroll
            for (int nt = 0; nt < NT_H; nt++)
                #pragma unroll
                for (int c = 0; c < 4; c++) acc[mt][nt][c] = 0.f;

        const int aoff = (rm + g) * AST + tg;
        const int boff = (cn + g) * AST + tg;

        for (int k = 0; k < NCHUNK; k++) {
            asm volatile("cp.async.wait_group %0;" :: "n"(STAGES - 2) : "memory");
            __syncthreads();
            if (k + STAGES - 1 < NCHUNK) issue(k + STAGES - 1, (k + STAGES - 1) & (STAGES - 1));
            asm volatile("cp.async.commit_group;" ::: "memory");

            const float* As = sm + OFF_STG + (k & (STAGES - 1)) * STG_FLTS;
            const float* ap = As + aoff;
            const float* bp = As + M_TILE * AST + boff;

            #pragma unroll
            for (int ks = 0; ks < KC; ks += 8) {
                uint32_t bf[NT_H][2];
                #pragma unroll
                for (int nt = 0; nt < NT_H; nt++) {
                    bf[nt][0] = f2tf32(bp[nt * 8 * AST + ks]);
                    bf[nt][1] = f2tf32(bp[nt * 8 * AST + ks + 4]);
                }
                #pragma unroll
                for (int mt = 0; mt < 4; mt++) {
                    uint32_t af[4];
                    af[0] = f2tf32(ap[mt * 16 * AST + ks]);
                    af[1] = f2tf32(ap[(mt * 16 + 8) * AST + ks]);
                    af[2] = f2tf32(ap[mt * 16 * AST + ks + 4]);
                    af[3] = f2tf32(ap[(mt * 16 + 8) * AST + ks + 4]);
                    #pragma unroll
                    for (int nt = 0; nt < NT_H; nt++)
                        mma_tf32(acc[mt][nt], af, bf[nt]);
                }
            }
        }

        // epilogue pass 1
        float bb[NT_H][2];
        #pragma unroll
        for (int nt = 0; nt < NT_H; nt++) {
            bb[nt][0] = sm[OFF_BIAS + cn + nt * 8 + tg * 2];
            bb[nt][1] = sm[OFF_BIAS + cn + nt * 8 + tg * 2 + 1];
        }
        #pragma unroll
        for (int mt = 0; mt < 4; mt++) {
            #pragma unroll
            for (int h = 0; h < 2; h++) {
                float t = 0.f, zz = 0.f;
                #pragma unroll
                for (int nt = 0; nt < NT_H; nt++) {
                    const float z0 = acc[mt][nt][h * 2]     - bb[nt][0];
                    const float z1 = acc[mt][nt][h * 2 + 1] - bb[nt][1];
                    t += z0 + z1;
                    zz = fmaf(z0, z0, zz);
                    zz = fmaf(z1, z1, zz);
                }
                #pragma unroll
                for (int o = 1; o <= 2; o <<= 1) {
                    t  += __shfl_xor_sync(0xffffffffu, t,  o);
                    zz += __shfl_xor_sync(0xffffffffu, zz, o);
                }
                if (tg == 0) {
                    const int rloc = rm + mt * 16 + g + h * 8;
                    sm[OFF_PT  + wcH * 128 + rloc] = t;
                    sm[OFF_PZZ + wcH * 128 + rloc] = zz;
                }
            }
        }
        __syncthreads();

        if (tid < 128) {
            const float t  = sm[OFF_PT + tid] + sm[OFF_PT + 128 + tid] + sm[OFF_PT + 256 + tid];
            const float zz = sm[OFF_PZZ + tid] + sm[OFF_PZZ + 128 + tid] + sm[OFF_PZZ + 256 + tid];
            const float S = 0.1f, R2 = 0.02f, invN = 1.0f / 256.0f;
            const float tc = fminf(fmaxf(t, -S), S);
            const float d1 = (tc - t) * invN;
            const float s1 = fmaf(fmaf(256.f, d1, 2.f * t), d1, zz);
            const bool ok1 = s1 <= R2;
            const float znorm = sqrtf(fmaxf(zz, 1e-12f));
            const float scale = fminf(1.f, 0.141421356237309515f / znorm);
            const bool ok2 = fabsf(t) * scale <= S;
            const float denom = fmaxf(fmaf(256.f, zz, -t * t), 1e-12f);
            const float c3 = sqrtf((256.f * R2 - S * S) / denom);
            const float sp = (t > 0.f) ? S : ((t < 0.f) ? -S : 0.f);
            const float b3 = fmaf(-c3, t, sp) * invN;
            sm[OFF_AB + tid]       = ok1 ? 1.f : (ok2 ? scale : c3);
            sm[OFF_AB + 128 + tid] = ok1 ? d1  : (ok2 ? 0.f   : b3);
        }
        __syncthreads();

        // pass 2: stores
        #pragma unroll
        for (int mt = 0; mt < 4; mt++) {
            #pragma unroll
            for (int h = 0; h < 2; h++) {
                const int rloc  = rm + mt * 16 + g + h * 8;
                const float al  = sm[OFF_AB + rloc];
                const float be  = sm[OFF_AB + 128 + rloc];
                float* op = out + (size_t)(m0 + rloc) * N_OUT + cn + tg * 2;
                #pragma unroll
                for (int nt = 0; nt < NT_H; nt++) {
                    float2 v;
                    v.x = fmaf(al, acc[mt][nt][h * 2]     - bb[nt][0], be);
                    v.y = fmaf(al, acc[mt][nt][h * 2 + 1] - bb[nt][1], be);
                    *reinterpret_cast<float2*>(op + nt * 8) = v;
                }
            }
        }
    } else {
        // ================= FFMA warps: rows 128, cols [144,256) =================
        const int fw    = wid - 4;             // 0..3 -> 32-row slice
        const int rbase = fw * 32;
        const int gr    = lane & 3;            // 4 row groups x 8 contiguous rows
        const int gc    = lane >> 2;           // 8 col groups x 14 cols

        unsigned long long a2[8][7];           // [row i][col pair p] -> (col 2p, col 2p+1)
        #pragma unroll
        for (int i = 0; i < 8; i++)
            #pragma unroll
            for (int p = 0; p < 7; p++) a2[i][p] = 0ull;

        const int xoff = (rbase + gr * 8) * AST;           // + i*AST + k  (rows rbase+gr*8+i)
        const int woff = (CF0 + gc * 14) * AST;            // + (2p(+1))*AST + k

        for (int k = 0; k < NCHUNK; k++) {
            asm volatile("cp.async.wait_group %0;" :: "n"(STAGES - 2) : "memory");
            __syncthreads();
            if (k + STAGES - 1 < NCHUNK) issue(k + STAGES - 1, (k + STAGES - 1) & (STAGES - 1));
            asm volatile("cp.async.commit_group;" ::: "memory");

            const float* As = sm + OFF_STG + (k & (STAGES - 1)) * STG_FLTS;
            const float* xb = As + xoff;
            const float* wb = As + M_TILE * AST + woff;

            #pragma unroll 4
            for (int kk = 0; kk < KC; kk++) {
                unsigned long long wv[7];
                #pragma unroll
                for (int p = 0; p < 7; p++)
                    wv[p] = pack2(wb[(2 * p) * AST + kk], wb[(2 * p + 1) * AST + kk]);
                #pragma unroll
                for (int i = 0; i < 8; i++) {
                    const float xv = xb[i * AST + kk];     // FIX: contiguous rows (was i*8*AST)
                    const unsigned long long xd = pack2(xv, xv);
                    #pragma unroll
                    for (int p = 0; p < 7; p++)
                        a2[i][p] = fma2(xd, wv[p], a2[i][p]);
                }
            }
        }

        // epilogue pass 1
        float bf0[14];
        #pragma unroll
        for (int j = 0; j < 14; j++) bf0[j] = sm[OFF_BIAS + CF0 + gc * 14 + j];

        #pragma unroll
        for (int i = 0; i < 8; i++) {
            float t = 0.f, zz = 0.f;
            #pragma unroll
            for (int p = 0; p < 7; p++) {
                float lo, hi;
                unpack2(a2[i][p], lo, hi);
                const float z0 = lo - bf0[2 * p];
                const float z1 = hi - bf0[2 * p + 1];
                t += z0 + z1;
                zz = fmaf(z0, z0, zz);
                zz = fmaf(z1, z1, zz);
            }
            #pragma unroll
            for (int o = 4; o <= 16; o <<= 1) {            // reduce over gc (8 lanes)
                t  += __shfl_xor_sync(0xffffffffu, t,  o);
                zz += __shfl_xor_sync(0xffffffffu, zz, o);
            }
            if (gc == 0) {
                const int rloc = rbase + gr * 8 + i;
                sm[OFF_PT  + 256 + rloc] = t;              // slot 2
                sm[OFF_PZZ + 256 + rloc] = zz;
            }
        }
        __syncthreads();   // matches HMMA warps' first epilogue barrier
        __syncthreads();   // matches HMMA warps' second barrier (AB computed by warps 0-3)

        // pass 2: stores
        #pragma unroll
        for (int i = 0; i < 8; i++) {
            const int rloc = rbase + gr * 8 + i;
            const float al = sm[OFF_AB + rloc];
            const float be = sm[OFF_AB + 128 + rloc];
            float* op = out + (size_t)(m0 + rloc) * N_OUT + CF0 + gc * 14;
            #pragma unroll
            for (int p = 0; p < 7; p++) {
                float lo, hi;
                unpack2(a2[i][p], lo, hi);
                float2 v;
                v.x = fmaf(al, lo - bf0[2 * p],     be);
                v.y = fmaf(al, hi - bf0[2 * p + 1], be);
                *reinterpret_cast<float2*>(op + 2 * p) = v;
            }
        }
    }
}

extern "C" void kernel_launch(void* const* d_in, const int* in_sizes, int n_in,
                              void* d_out, int out_size) {
    const float* x = (const float*)d_in[0];   // [B, 512]
    const float* W = (const float*)d_in[1];   // [256, 512]
    const float* b = (const float*)d_in[2];   // [256]
    float* out = (float*)d_out;               // [B, 256]
    const int Brows = in_sizes[0] / K_DIM;

    static bool attr_set = false;
    if (!attr_set) {
        cudaFuncSetAttribute(fused_gemm_proj_kernel,
                             cudaFuncAttributeMaxDynamicSharedMemorySize, SMEM_BYTES);
        attr_set = true;
    }
    fused_gemm_proj_kernel<<<Brows / M_TILE, NTHREADS, SMEM_BYTES>>>(x, W, b, out);
}

// round 14
// speedup vs baseline: 2.7754x; 2.7754x over previous
#include <cuda_runtime.h>
#include <cstdint>
#include <cstddef>

// ---------------- tile config ----------------
#define M_TILE 64
#define N_OUT  256
#define K_DIM  512
#define KC     16                  // K per pipeline stage = one fp16 MMA k-step
#define NCHUNK (K_DIM / KC)        // 32
#define STAGES 4
#define AST    20                  // padded fp32 stride -> conflict-free frags
#define NTHREADS 256

// smem float offsets
#define OFF_BIAS 0                 // 256 floats
#define OFF_PT   256               // [4][64] per-n-warp partial t
#define OFF_PZZ  512               // [4][64] partial zz
#define OFF_AB   768               // [2][64] alpha, beta
#define OFF_STG  1024
#define STG_FLTS (M_TILE * AST + N_OUT * AST)   // 1280 + 5120 = 6400
#define SMEM_FLTS (OFF_STG + STAGES * STG_FLTS) // 26624
#define SMEM_BYTES (SMEM_FLTS * 4)              // 106496 -> 2 CTAs/SM

__device__ __forceinline__ uint32_t s2u(const void* p) {
    uint32_t a;
    asm("{ .reg .u64 t; cvta.to.shared.u64 t, %1; cvt.u32.u64 %0, t; }" : "=r"(a) : "l"(p));
    return a;
}
__device__ __forceinline__ void cp16(uint32_t dst, const float* src) {
    asm volatile("cp.async.cg.shared.global [%0], [%1], 16;" :: "r"(dst), "l"(src) : "memory");
}
// pack two f32 -> f16x2 reg: lo half = even-k element, hi half = odd-k element
__device__ __forceinline__ uint32_t f16x2(float2 v) {
    uint32_t r;
    asm("cvt.rn.f16x2.f32 %0, %1, %2;" : "=r"(r) : "f"(v.y), "f"(v.x));
    return r;
}
__device__ __forceinline__ void mma_f16(float* c, const uint32_t a[4], const uint32_t b[2]) {
    asm volatile(
        "mma.sync.aligned.m16n8k16.row.col.f32.f16.f16.f32 "
        "{%0,%1,%2,%3}, {%4,%5,%6,%7}, {%8,%9}, {%0,%1,%2,%3};"
        : "+f"(c[0]), "+f"(c[1]), "+f"(c[2]), "+f"(c[3])
        : "r"(a[0]), "r"(a[1]), "r"(a[2]), "r"(a[3]), "r"(b[0]), "r"(b[1]));
}

__global__ void __launch_bounds__(NTHREADS, 2)
fused_gemm_proj_kernel(const float* __restrict__ x,
                       const float* __restrict__ Wm,
                       const float* __restrict__ bvec,
                       float* __restrict__ out) {
    extern __shared__ __align__(128) float sm[];
    const uint32_t sb = s2u(sm);
    const int tid  = threadIdx.x;
    const int wid  = tid >> 5;
    const int lane = tid & 31;
    const int g    = lane >> 2;      // 0..7
    const int tg   = lane & 3;       // 0..3
    const int wr   = wid & 1;        // warp m index (2): 32-row slices
    const int wc   = wid >> 1;       // warp n index (4): 64-col slices
    const int rm   = wr * 32;
    const int cn   = wc * 64;
    const int m0   = blockIdx.x * M_TILE;

    sm[OFF_BIAS + tid] = bvec[tid];

    // ---- cp.async stage issue (256 threads, 5 x 16B each) ----
    auto issue = [&](int k, int s) {
        const int k0 = k * KC;
        const uint32_t as = sb + (OFF_STG + s * STG_FLTS) * 4;
        const uint32_t bs = as + M_TILE * AST * 4;
        {                                              // A: 256 x 16B chunks
            const int r = tid >> 2, c = (tid & 3) * 4;
            cp16(as + (r * AST + c) * 4, x + (size_t)(m0 + r) * K_DIM + k0 + c);
        }
        #pragma unroll
        for (int i = 0; i < 4; i++) {                  // W: 1024 x 16B chunks
            const int ch = tid + NTHREADS * i;
            const int n = ch >> 2, c = (ch & 3) * 4;
            cp16(bs + (n * AST + c) * 4, Wm + (size_t)n * K_DIM + k0 + c);
        }
    };

    float acc[2][8][4];
    #pragma unroll
    for (int mt = 0; mt < 2; mt++)
        #pragma unroll
        for (int nt = 0; nt < 8; nt++)
            #pragma unroll
            for (int c = 0; c < 4; c++) acc[mt][nt][c] = 0.f;

    // prologue: fill STAGES-1 stages
    #pragma unroll
    for (int s = 0; s < STAGES - 1; s++) {
        issue(s, s);
        asm volatile("cp.async.commit_group;" ::: "memory");
    }

    // fragment bases: even float offsets -> 8B-aligned float2 loads
    const int aoff = (rm + g) * AST + 2 * tg;   // + mt*16*AST (+8*AST) (+8)
    const int boff = (cn + g) * AST + 2 * tg;   // + nt*8*AST (+8)

    for (int k = 0; k < NCHUNK; k++) {
        asm volatile("cp.async.wait_group %0;" :: "n"(STAGES - 2) : "memory");
        __syncthreads();
        if (k + STAGES - 1 < NCHUNK) issue(k + STAGES - 1, (k + STAGES - 1) & (STAGES - 1));
        asm volatile("cp.async.commit_group;" ::: "memory");

        const float* As = sm + OFF_STG + (k & (STAGES - 1)) * STG_FLTS;
        const float* ap = As + aoff;
        const float* bp = As + M_TILE * AST + boff;

        // single K=16 fp16 MMA step per chunk
        uint32_t bf[8][2];
        #pragma unroll
        for (int nt = 0; nt < 8; nt++) {
            bf[nt][0] = f16x2(*reinterpret_cast<const float2*>(bp + nt * 8 * AST));
            bf[nt][1] = f16x2(*reinterpret_cast<const float2*>(bp + nt * 8 * AST + 8));
        }
        #pragma unroll
        for (int mt = 0; mt < 2; mt++) {
            uint32_t af[4];
            af[0] = f16x2(*reinterpret_cast<const float2*>(ap + mt * 16 * AST));
            af[1] = f16x2(*reinterpret_cast<const float2*>(ap + (mt * 16 + 8) * AST));
            af[2] = f16x2(*reinterpret_cast<const float2*>(ap + mt * 16 * AST + 8));
            af[3] = f16x2(*reinterpret_cast<const float2*>(ap + (mt * 16 + 8) * AST + 8));
            #pragma unroll
            for (int nt = 0; nt < 8; nt++)
                mma_f16(acc[mt][nt], af, bf[nt]);
        }
    }

    // ---------------- fused projection epilogue ----------------
    float bb[8][2];
    #pragma unroll
    for (int nt = 0; nt < 8; nt++) {
        bb[nt][0] = sm[OFF_BIAS + cn + nt * 8 + tg * 2];
        bb[nt][1] = sm[OFF_BIAS + cn + nt * 8 + tg * 2 + 1];
    }

    // pass 1: per-row partials over this warp's 64 columns
    #pragma unroll
    for (int mt = 0; mt < 2; mt++) {
        #pragma unroll
        for (int h = 0; h < 2; h++) {
            float t = 0.f, zz = 0.f;
            #pragma unroll
            for (int nt = 0; nt < 8; nt++) {
                const float z0 = acc[mt][nt][h * 2]     - bb[nt][0];
                const float z1 = acc[mt][nt][h * 2 + 1] - bb[nt][1];
                t += z0 + z1;
                zz = fmaf(z0, z0, zz);
                zz = fmaf(z1, z1, zz);
            }
            #pragma unroll
            for (int o = 1; o <= 2; o <<= 1) {          // reduce over tg (4 lanes)
                t  += __shfl_xor_sync(0xffffffffu, t,  o);
                zz += __shfl_xor_sync(0xffffffffu, zz, o);
            }
            if (tg == 0) {
                const int rloc = rm + mt * 16 + g + h * 8;
                sm[OFF_PT  + wc * 64 + rloc] = t;
                sm[OFF_PZZ + wc * 64 + rloc] = zz;
            }
        }
    }
    __syncthreads();

    if (tid < 64) {
        const float t  = sm[OFF_PT + tid] + sm[OFF_PT + 64 + tid] +
                         sm[OFF_PT + 128 + tid] + sm[OFF_PT + 192 + tid];
        const float zz = sm[OFF_PZZ + tid] + sm[OFF_PZZ + 64 + tid] +
                         sm[OFF_PZZ + 128 + tid] + sm[OFF_PZZ + 192 + tid];
        const float S = 0.1f, R2 = 0.02f, invN = 1.0f / 256.0f;
        const float tc = fminf(fmaxf(t, -S), S);
        const float d1 = (tc - t) * invN;
        const float s1 = fmaf(fmaf(256.f, d1, 2.f * t), d1, zz);
        const bool ok1 = s1 <= R2;
        const float znorm = sqrtf(fmaxf(zz, 1e-12f));
        const float scale = fminf(1.f, 0.141421356237309515f / znorm);
        const bool ok2 = fabsf(t) * scale <= S;
        const float denom = fmaxf(fmaf(256.f, zz, -t * t), 1e-12f);
        const float c3 = sqrtf((256.f * R2 - S * S) / denom);
        const float sp = (t > 0.f) ? S : ((t < 0.f) ? -S : 0.f);
        const float b3 = fmaf(-c3, t, sp) * invN;
        sm[OFF_AB + tid]      = ok1 ? 1.f : (ok2 ? scale : c3);   // alpha
        sm[OFF_AB + 64 + tid] = ok1 ? d1  : (ok2 ? 0.f   : b3);   // beta
    }
    __syncthreads();

    // pass 2: y = alpha*z + beta, float2 stores
    #pragma unroll
    for (int mt = 0; mt < 2; mt++) {
        #pragma unroll
        for (int h = 0; h < 2; h++) {
            const int rloc  = rm + mt * 16 + g + h * 8;
            const float al  = sm[OFF_AB + rloc];
            const float be  = sm[OFF_AB + 64 + rloc];
            float* op = out + (size_t)(m0 + rloc) * N_OUT + cn + tg * 2;
            #pragma unroll
            for (int nt = 0; nt < 8; nt++) {
                float2 v;
                v.x = fmaf(al, acc[mt][nt][h * 2]     - bb[nt][0], be);
                v.y = fmaf(al, acc[mt][nt][h * 2 + 1] - bb[nt][1], be);
                *reinterpret_cast<float2*>(op + nt * 8) = v;
            }
        }
    }
}

extern "C" void kernel_launch(void* const* d_in, const int* in_sizes, int n_in,
                              void* d_out, int out_size) {
    const float* x = (const float*)d_in[0];   // [B, 512]
    const float* W = (const float*)d_in[1];   // [256, 512]
    const float* b = (const float*)d_in[2];   // [256]
    float* out = (float*)d_out;               // [B, 256]
    const int Brows = in_sizes[0] / K_DIM;

    static bool attr_set = false;
    if (!attr_set) {
        cudaFuncSetAttribute(fused_gemm_proj_kernel,
                             cudaFuncAttributeMaxDynamicSharedMemorySize, SMEM_BYTES);
        attr_set = true;
    }
    fused_gemm_proj_kernel<<<Brows / M_TILE, NTHREADS, SMEM_BYTES>>>(x, W, b, out);
}